// round 6
// baseline (speedup 1.0000x reference)
#include <cuda_runtime.h>
#include <cuda_bf16.h>
#include <math.h>
#include <cstdint>

// Problem constants
#define Ld 4
#define Nn 2048
#define DIN 1024
#define Hh 8
#define DHd 64
#define INNER 512
#define DOUT 1024
#define SCALEF 0.125f   // 64^-0.5

// ---------------------------------------------------------------------------
// Scratch (device globals) — all intermediates live as bf16 hi/lo pairs
// ---------------------------------------------------------------------------
__device__ __nv_bfloat16 gxh[(size_t)Ld*Nn*DIN], gxl[(size_t)Ld*Nn*DIN];
__device__ __nv_bfloat16 gwqh[INNER*DIN], gwql[INNER*DIN];
__device__ __nv_bfloat16 gwkh[INNER*DIN], gwkl[INNER*DIN];
__device__ __nv_bfloat16 gwvh[INNER*DIN], gwvl[INNER*DIN];
__device__ __nv_bfloat16 gwoh[DOUT*INNER], gwol[DOUT*INNER];
__device__ __nv_bfloat16 gqh[(size_t)Ld*Hh*Nn*DHd], gql[(size_t)Ld*Hh*Nn*DHd];
__device__ __nv_bfloat16 gkh[(size_t)Ld*Hh*Nn*DHd], gkl[(size_t)Ld*Hh*Nn*DHd];
__device__ __nv_bfloat16 gvh[(size_t)Ld*Hh*Nn*DHd], gvl[(size_t)Ld*Hh*Nn*DHd];
__device__ __nv_bfloat16 gaoh[(size_t)Ld*Nn*INNER], gaol[(size_t)Ld*Nn*INNER];
__device__ float g_mask[Ld*Nn];

// ===========================================================================
// Helpers
// ===========================================================================
__device__ __forceinline__ void mma_bf16(float* c, const uint32_t* a, const uint32_t* b) {
    asm volatile(
        "mma.sync.aligned.m16n8k16.row.col.f32.bf16.bf16.f32 "
        "{%0,%1,%2,%3}, {%4,%5,%6,%7}, {%8,%9}, {%0,%1,%2,%3};"
        : "+f"(c[0]), "+f"(c[1]), "+f"(c[2]), "+f"(c[3])
        : "r"(a[0]), "r"(a[1]), "r"(a[2]), "r"(a[3]), "r"(b[0]), "r"(b[1]));
}

#define LDMX4(r, a) \
    asm volatile("ldmatrix.sync.aligned.m8n8.x4.shared.b16 {%0,%1,%2,%3}, [%4];" \
        : "=r"((r)[0]), "=r"((r)[1]), "=r"((r)[2]), "=r"((r)[3]) : "r"(a))

#define LDMX4T(r, a) \
    asm volatile("ldmatrix.sync.aligned.m8n8.x4.trans.shared.b16 {%0,%1,%2,%3}, [%4];" \
        : "=r"((r)[0]), "=r"((r)[1]), "=r"((r)[2]), "=r"((r)[3]) : "r"(a))

__device__ __forceinline__ uint32_t smem_to_u32(const void* p) {
    uint32_t a;
    asm("{ .reg .u64 t; cvta.to.shared.u64 t, %1; cvt.u32.u64 %0, t; }" : "=r"(a) : "l"(p));
    return a;
}

__device__ __forceinline__ uint32_t packbf2(float x, float y) {
    __nv_bfloat162 h = __floats2bfloat162_rn(x, y);
    return *reinterpret_cast<uint32_t*>(&h);
}

// Fast exp on the FMA pipe (no MUFU); handles big-negative mask bias via clamp.
__device__ __forceinline__ float fast_exp(float x) {
    float t = fmaxf(x * 1.4426950408889634f, -126.0f);
    int ni = __float2int_rn(t);
    float r = t - (float)ni;
    float p = 1.5403530e-4f;
    p = fmaf(p, r, 1.3333558e-3f);
    p = fmaf(p, r, 9.6181291e-3f);
    p = fmaf(p, r, 5.5504109e-2f);
    p = fmaf(p, r, 2.4022651e-1f);
    p = fmaf(p, r, 6.9314718e-1f);
    p = fmaf(p, r, 1.0f);
    return __int_as_float(__float_as_int(p) + (ni << 23));
}

// ===========================================================================
// Mask dtype detection + normalization
// ===========================================================================
__global__ void mask_convert_kernel(const unsigned char* __restrict__ raw) {
    __shared__ int flag_float, flag_big;
    int tid = threadIdx.x;
    if (tid == 0) { flag_float = 0; flag_big = 0; }
    __syncthreads();
    const unsigned int* w = (const unsigned int*)raw;
    for (int i = tid; i < 2048; i += blockDim.x) {
        unsigned int v = w[i];
        if (v == 0x3F800000u) atomicOr(&flag_float, 1);
        else if (v > 1u)      atomicOr(&flag_big, 1);
    }
    __syncthreads();
    bool isfloat = (flag_float != 0);
    bool isbyte  = (!isfloat) && (flag_big != 0);
    for (int i = tid; i < Ld*Nn; i += blockDim.x) {
        unsigned int v;
        if (isbyte) v = raw[i];
        else        v = ((const unsigned int*)raw)[i];
        g_mask[i] = (v != 0u) ? 1.0f : 0.0f;
    }
}

// ===========================================================================
// One-time fp32 -> bf16 hi/lo split (elementwise, float4-vectorized)
// ===========================================================================
__global__ void split_kernel(const float* __restrict__ in,
                             __nv_bfloat16* __restrict__ hi,
                             __nv_bfloat16* __restrict__ lo, int n4) {
    int i = blockIdx.x * 256 + threadIdx.x;
    if (i >= n4) return;
    float4 v = ((const float4*)in)[i];
    __nv_bfloat16 h0 = __float2bfloat16_rn(v.x);
    __nv_bfloat16 h1 = __float2bfloat16_rn(v.y);
    __nv_bfloat16 h2 = __float2bfloat16_rn(v.z);
    __nv_bfloat16 h3 = __float2bfloat16_rn(v.w);
    ((__nv_bfloat162*)hi)[i*2]   = __halves2bfloat162(h0, h1);
    ((__nv_bfloat162*)hi)[i*2+1] = __halves2bfloat162(h2, h3);
    ((__nv_bfloat162*)lo)[i*2]   = __halves2bfloat162(
        __float2bfloat16_rn(v.x - __bfloat162float(h0)),
        __float2bfloat16_rn(v.y - __bfloat162float(h1)));
    ((__nv_bfloat162*)lo)[i*2+1] = __halves2bfloat162(
        __float2bfloat16_rn(v.z - __bfloat162float(h2)),
        __float2bfloat16_rn(v.w - __bfloat162float(h3)));
}

// ===========================================================================
// bf16 GEMM core: C[128 x 128] = A[128 x K] * B[128 x K]^T
// A/B given as pre-split hi/lo bf16, row-major. 256 threads, 8 warps (4m x 2n),
// warp tile m32 x n64. 3-term split accumulate in fp32. ldmatrix everywhere.
// ===========================================================================
#define GS_ATS 72
#define GS_TILE (128 * GS_ATS)
#define GS_BYTES (4 * GS_TILE * 2)

struct CFrag2 { float c[2][8][4]; };

__device__ __forceinline__ void gemm128(
    const __nv_bfloat16* __restrict__ Ah_g, const __nv_bfloat16* __restrict__ Al_g, int lda,
    const __nv_bfloat16* __restrict__ Bh_g, const __nv_bfloat16* __restrict__ Bl_g, int ldb,
    int Kdim, __nv_bfloat16* sm, CFrag2& f)
{
    const int tid = threadIdx.x, lane = tid & 31, wid = tid >> 5;
    const int warp_m = wid >> 1, warp_n = wid & 1;
    const int lrow = lane & 15, lcol = (lane >> 4) << 3;
    const int brow = (lane & 7) + ((lane >> 3) & 1) * 8;

    __nv_bfloat16* Ah = sm;
    __nv_bfloat16* Al = sm + GS_TILE;
    __nv_bfloat16* Bh = sm + 2 * GS_TILE;
    __nv_bfloat16* Bl = sm + 3 * GS_TILE;
    const uint32_t ah_u = smem_to_u32(Ah), al_u = smem_to_u32(Al);
    const uint32_t bh_u = smem_to_u32(Bh), bl_u = smem_to_u32(Bl);

    #pragma unroll
    for (int mt = 0; mt < 2; mt++)
        #pragma unroll
        for (int nt = 0; nt < 8; nt++)
            #pragma unroll
            for (int i = 0; i < 4; i++) f.c[mt][nt][i] = 0.0f;

    for (int k0 = 0; k0 < Kdim; k0 += 64) {
        #pragma unroll
        for (int it = 0; it < 4; it++) {
            int t = tid + it * 256;
            int r = t >> 3, c8 = (t & 7) << 3;
            *(uint4*)(Ah + r * GS_ATS + c8) = *(const uint4*)(Ah_g + (size_t)r * lda + k0 + c8);
            *(uint4*)(Al + r * GS_ATS + c8) = *(const uint4*)(Al_g + (size_t)r * lda + k0 + c8);
            *(uint4*)(Bh + r * GS_ATS + c8) = *(const uint4*)(Bh_g + (size_t)r * ldb + k0 + c8);
            *(uint4*)(Bl + r * GS_ATS + c8) = *(const uint4*)(Bl_g + (size_t)r * ldb + k0 + c8);
        }
        __syncthreads();

        #pragma unroll
        for (int ks = 0; ks < 4; ks++) {
            const int kk = ks * 16;
            uint32_t ahf[2][4], alf[2][4];
            #pragma unroll
            for (int mt = 0; mt < 2; mt++) {
                uint32_t off = (uint32_t)((warp_m*32 + mt*16 + lrow) * GS_ATS + kk + lcol) * 2;
                LDMX4(ahf[mt], ah_u + off);
                LDMX4(alf[mt], al_u + off);
            }
            #pragma unroll
            for (int ng = 0; ng < 4; ng++) {
                uint32_t off = (uint32_t)((warp_n*64 + ng*16 + brow) * GS_ATS + kk + lcol) * 2;
                uint32_t kh4[4], kl4[4];
                LDMX4(kh4, bh_u + off);
                LDMX4(kl4, bl_u + off);
                uint32_t b0h[2] = {kh4[0], kh4[2]}, b1h[2] = {kh4[1], kh4[3]};
                uint32_t b0l[2] = {kl4[0], kl4[2]}, b1l[2] = {kl4[1], kl4[3]};
                #pragma unroll
                for (int mt = 0; mt < 2; mt++) {
                    mma_bf16(f.c[mt][ng*2],   ahf[mt], b0h);
                    mma_bf16(f.c[mt][ng*2],   ahf[mt], b0l);
                    mma_bf16(f.c[mt][ng*2],   alf[mt], b0h);
                    mma_bf16(f.c[mt][ng*2+1], ahf[mt], b1h);
                    mma_bf16(f.c[mt][ng*2+1], ahf[mt], b1l);
                    mma_bf16(f.c[mt][ng*2+1], alf[mt], b1h);
                }
            }
        }
        __syncthreads();
    }
}

// ---------------------------------------------------------------------------
// QKV projection: grid (4 e-tiles, 64 m-tiles, 3 matrices). Output written
// head-split as bf16 hi/lo; q pre-scaled by SCALEF.
// ---------------------------------------------------------------------------
__global__ __launch_bounds__(256)
void qkv_tc_kernel() {
    extern __shared__ __nv_bfloat16 smg[];
    const int which = blockIdx.z;
    const __nv_bfloat16 *Wh, *Wl;
    __nv_bfloat16 *oh, *ol;
    float scale;
    if (which == 0)      { Wh = gwqh; Wl = gwql; oh = gqh; ol = gql; scale = SCALEF; }
    else if (which == 1) { Wh = gwkh; Wl = gwkl; oh = gkh; ol = gkl; scale = 1.0f; }
    else                 { Wh = gwvh; Wl = gwvl; oh = gvh; ol = gvl; scale = 1.0f; }

    const int m0 = blockIdx.y * 128, e0 = blockIdx.x * 128;
    CFrag2 f;
    gemm128(gxh + (size_t)m0 * DIN, gxl + (size_t)m0 * DIN, DIN,
            Wh + (size_t)e0 * DIN, Wl + (size_t)e0 * DIN, DIN, DIN, smg, f);

    const int tid = threadIdx.x, lane = tid & 31, wid = tid >> 5;
    const int gid = lane >> 2, tig = lane & 3;
    const int warp_m = wid >> 1, warp_n = wid & 1;
    const int head = (e0 >> 6) + warp_n;

    #pragma unroll
    for (int mt = 0; mt < 2; mt++) {
        #pragma unroll
        for (int rr = 0; rr < 2; rr++) {
            int m = m0 + warp_m*32 + mt*16 + gid + rr*8;
            int l = m >> 11, n = m & 2047;
            size_t base = ((size_t)((l*Hh + head)*Nn + n)) * DHd;
            #pragma unroll
            for (int nt = 0; nt < 8; nt++) {
                int d = nt*8 + tig*2;
                float v0 = f.c[mt][nt][rr*2]   * scale;
                float v1 = f.c[mt][nt][rr*2+1] * scale;
                __nv_bfloat16 h0 = __float2bfloat16_rn(v0);
                __nv_bfloat16 h1 = __float2bfloat16_rn(v1);
                *(__nv_bfloat162*)(oh + base + d) = __halves2bfloat162(h0, h1);
                *(__nv_bfloat162*)(ol + base + d) = __halves2bfloat162(
                    __float2bfloat16_rn(v0 - __bfloat162float(h0)),
                    __float2bfloat16_rn(v1 - __bfloat162float(h1)));
            }
        }
    }
}

// ---------------------------------------------------------------------------
// Output projection: grid (8 o-tiles, 64 m-tiles), fp32 out + bias
// ---------------------------------------------------------------------------
__global__ __launch_bounds__(256)
void oproj_tc_kernel(const float* __restrict__ bo, float* __restrict__ out) {
    extern __shared__ __nv_bfloat16 smg[];
    const int m0 = blockIdx.y * 128, o0 = blockIdx.x * 128;
    CFrag2 f;
    gemm128(gaoh + (size_t)m0 * INNER, gaol + (size_t)m0 * INNER, INNER,
            gwoh + (size_t)o0 * INNER, gwol + (size_t)o0 * INNER, INNER, INNER, smg, f);

    const int tid = threadIdx.x, lane = tid & 31, wid = tid >> 5;
    const int gid = lane >> 2, tig = lane & 3;
    const int warp_m = wid >> 1, warp_n = wid & 1;

    #pragma unroll
    for (int mt = 0; mt < 2; mt++) {
        #pragma unroll
        for (int rr = 0; rr < 2; rr++) {
            int m = m0 + warp_m*32 + mt*16 + gid + rr*8;
            float* dst = out + (size_t)m * DOUT + o0;
            #pragma unroll
            for (int nt = 0; nt < 8; nt++) {
                int col = warp_n*64 + nt*8 + tig*2;
                float2 b = *(const float2*)(bo + o0 + col);
                *(float2*)(dst + col) = make_float2(f.c[mt][nt][rr*2]   + b.x,
                                                    f.c[mt][nt][rr*2+1] + b.y);
            }
        }
    }
}

// ===========================================================================
// Flash attention on HMMA, bf16 hi/lo inputs (no conversion in mainloop).
// 64 q-rows per CTA, 4 warps (16 rows each), 64-key tiles, fast_exp softmax.
// ===========================================================================
#define ATS 72
#define A_QH 0
#define A_QL 4608
#define A_KH 9216
#define A_KL 13824
#define A_VH 18432
#define A_VL 23040
#define A_BIAS_BYTES 55296
#define A_SMEM_BYTES  55552

__global__ __launch_bounds__(128, 3)
void attn_mma_kernel() {
    extern __shared__ char sb[];
    __nv_bfloat16* Qh = (__nv_bfloat16*)sb;
    __nv_bfloat16* Ql = Qh + A_QL;
    __nv_bfloat16* Kh = Qh + A_KH;
    __nv_bfloat16* Kl = Qh + A_KL;
    __nv_bfloat16* Vh = Qh + A_VH;
    __nv_bfloat16* Vl = Qh + A_VL;
    float* bias = (float*)(sb + A_BIAS_BYTES);

    const int qb = blockIdx.x, h = blockIdx.y, l = blockIdx.z;
    const int tid = threadIdx.x;
    const int wid = tid >> 5, lane = tid & 31;
    const int gid = lane >> 2, tig = lane & 3;
    const int q0 = qb * 64;
    const size_t hb = (size_t)((l*Hh + h) * Nn) * DHd;

    // Load Q hi/lo (scale already folded in by qkv kernel)
    #pragma unroll
    for (int it = 0; it < 4; it++) {
        int t = tid + it * 128;
        int r = t >> 3, c8 = (t & 7) << 3;
        *(uint4*)(Qh + r*ATS + c8) = *(const uint4*)(gqh + hb + (size_t)(q0 + r)*DHd + c8);
        *(uint4*)(Ql + r*ATS + c8) = *(const uint4*)(gql + hb + (size_t)(q0 + r)*DHd + c8);
    }

    // ldmatrix lane offsets
    const int lrow = lane & 15, lcol = (lane >> 4) << 3;
    const int brow = (lane & 7) + ((lane >> 3) & 1) * 8;
    const uint32_t qh_u = smem_to_u32(Qh), ql_u = smem_to_u32(Ql);
    const uint32_t kh_u = smem_to_u32(Kh), kl_u = smem_to_u32(Kl);
    // V trans ldmatrix offsets (validated in R5)
    const int l4 = lane & 7, grp = lane >> 3;
    const int vrow = l4 + ((grp & 1) << 3);
    const int vcol = (grp >> 1) << 3;
    const uint32_t vh_base = smem_to_u32(Vh) + (uint32_t)(vrow * ATS + vcol) * 2;
    const uint32_t vl_base = smem_to_u32(Vl) + (uint32_t)(vrow * ATS + vcol) * 2;

    float o[8][4];
    #pragma unroll
    for (int nt = 0; nt < 8; nt++)
        #pragma unroll
        for (int i = 0; i < 4; i++) o[nt][i] = 0.0f;
    float m0 = -1e30f, m1 = -1e30f, l0 = 0.0f, l1 = 0.0f;

    for (int kb = 0; kb < Nn / 64; kb++) {
        __syncthreads();
        #pragma unroll
        for (int it = 0; it < 4; it++) {
            int t = tid + it * 128;
            int r = t >> 3, c8 = (t & 7) << 3;
            size_t src = hb + (size_t)(kb*64 + r) * DHd + c8;
            *(uint4*)(Kh + r*ATS + c8) = *(const uint4*)(gkh + src);
            *(uint4*)(Kl + r*ATS + c8) = *(const uint4*)(gkl + src);
            *(uint4*)(Vh + r*ATS + c8) = *(const uint4*)(gvh + src);
            *(uint4*)(Vl + r*ATS + c8) = *(const uint4*)(gvl + src);
        }
        if (tid < 64) bias[tid] = (g_mask[l*Nn + kb*64 + tid] - 1.0f) * 1e9f;
        __syncthreads();

        // ---- S = Q K^T via ldmatrix ----
        float sfr[8][4];
        #pragma unroll
        for (int nt = 0; nt < 8; nt++)
            #pragma unroll
            for (int i = 0; i < 4; i++) sfr[nt][i] = 0.0f;

        #pragma unroll
        for (int ks = 0; ks < 4; ks++) {
            const int kk = ks * 16;
            uint32_t aqh[4], aql[4];
            uint32_t qoff = (uint32_t)((wid*16 + lrow) * ATS + kk + lcol) * 2;
            LDMX4(aqh, qh_u + qoff);
            LDMX4(aql, ql_u + qoff);
            #pragma unroll
            for (int ng = 0; ng < 4; ng++) {
                uint32_t koff = (uint32_t)((ng*16 + brow) * ATS + kk + lcol) * 2;
                uint32_t kh4[4], kl4[4];
                LDMX4(kh4, kh_u + koff);
                LDMX4(kl4, kl_u + koff);
                uint32_t b0h[2] = {kh4[0], kh4[2]}, b1h[2] = {kh4[1], kh4[3]};
                uint32_t b0l[2] = {kl4[0], kl4[2]}, b1l[2] = {kl4[1], kl4[3]};
                mma_bf16(sfr[ng*2],   aqh, b0h);
                mma_bf16(sfr[ng*2],   aqh, b0l);
                mma_bf16(sfr[ng*2],   aql, b0h);
                mma_bf16(sfr[ng*2+1], aqh, b1h);
                mma_bf16(sfr[ng*2+1], aqh, b1l);
                mma_bf16(sfr[ng*2+1], aql, b1h);
            }
        }

        // ---- mask bias + row max ----
        float mx0 = -1e30f, mx1 = -1e30f;
        #pragma unroll
        for (int nt = 0; nt < 8; nt++) {
            float2 b2 = *(const float2*)(bias + nt*8 + tig*2);
            sfr[nt][0] += b2.x; sfr[nt][1] += b2.y;
            sfr[nt][2] += b2.x; sfr[nt][3] += b2.y;
            mx0 = fmaxf(mx0, fmaxf(sfr[nt][0], sfr[nt][1]));
            mx1 = fmaxf(mx1, fmaxf(sfr[nt][2], sfr[nt][3]));
        }
        mx0 = fmaxf(mx0, __shfl_xor_sync(0xFFFFFFFFu, mx0, 1));
        mx0 = fmaxf(mx0, __shfl_xor_sync(0xFFFFFFFFu, mx0, 2));
        mx1 = fmaxf(mx1, __shfl_xor_sync(0xFFFFFFFFu, mx1, 1));
        mx1 = fmaxf(mx1, __shfl_xor_sync(0xFFFFFFFFu, mx1, 2));

        float mn0 = fmaxf(m0, mx0), mn1 = fmaxf(m1, mx1);
        float sc0 = fast_exp(m0 - mn0), sc1 = fast_exp(m1 - mn1);
        m0 = mn0; m1 = mn1;

        // ---- P = exp(S - m); pack bf16 hi/lo fragments; row sums ----
        float rs0 = 0.0f, rs1 = 0.0f;
        uint32_t ph[8][2], pl[8][2];
        #pragma unroll
        for (int nt = 0; nt < 8; nt++) {
            float p0 = fast_exp(sfr[nt][0] - m0);
            float p1 = fast_exp(sfr[nt][1] - m0);
            float p2 = fast_exp(sfr[nt][2] - m1);
            float p3 = fast_exp(sfr[nt][3] - m1);
            rs0 += p0 + p1; rs1 += p2 + p3;
            __nv_bfloat16 h0 = __float2bfloat16_rn(p0);
            __nv_bfloat16 h1 = __float2bfloat16_rn(p1);
            __nv_bfloat16 h2 = __float2bfloat16_rn(p2);
            __nv_bfloat16 h3 = __float2bfloat16_rn(p3);
            ph[nt][0] = packbf2(__bfloat162float(h0), __bfloat162float(h1));
            ph[nt][1] = packbf2(__bfloat162float(h2), __bfloat162float(h3));
            pl[nt][0] = packbf2(p0 - __bfloat162float(h0), p1 - __bfloat162float(h1));
            pl[nt][1] = packbf2(p2 - __bfloat162float(h2), p3 - __bfloat162float(h3));
        }
        rs0 += __shfl_xor_sync(0xFFFFFFFFu, rs0, 1);
        rs0 += __shfl_xor_sync(0xFFFFFFFFu, rs0, 2);
        rs1 += __shfl_xor_sync(0xFFFFFFFFu, rs1, 1);
        rs1 += __shfl_xor_sync(0xFFFFFFFFu, rs1, 2);
        l0 = l0 * sc0 + rs0;
        l1 = l1 * sc1 + rs1;

        #pragma unroll
        for (int nt = 0; nt < 8; nt++) {
            o[nt][0] *= sc0; o[nt][1] *= sc0;
            o[nt][2] *= sc1; o[nt][3] *= sc1;
        }

        // ---- O += P V ----
        #pragma unroll
        for (int ks = 0; ks < 4; ks++) {
            uint32_t aph[4] = { ph[2*ks][0], ph[2*ks][1], ph[2*ks+1][0], ph[2*ks+1][1] };
            uint32_t apl[4] = { pl[2*ks][0], pl[2*ks][1], pl[2*ks+1][0], pl[2*ks+1][1] };
            #pragma unroll
            for (int dhc = 0; dhc < 4; dhc++) {
                uint32_t off = (uint32_t)(ks * 16 * ATS + dhc * 16) * 2;
                uint32_t bvh[4], bvl[4];
                LDMX4T(bvh, vh_base + off);
                LDMX4T(bvl, vl_base + off);
                int nt = dhc * 2;
                mma_bf16(o[nt],   aph, bvh);
                mma_bf16(o[nt],   aph, bvl);
                mma_bf16(o[nt],   apl, bvh);
                mma_bf16(o[nt+1], aph, bvh + 2);
                mma_bf16(o[nt+1], aph, bvl + 2);
                mma_bf16(o[nt+1], apl, bvh + 2);
            }
        }
    }

    // ---- epilogue: normalize, split hi/lo, write bf16 [L,N,H*DH] ----
    float inv0 = 1.0f / l0, inv1 = 1.0f / l1;
    int qr0 = q0 + wid*16 + gid;
    size_t b0i = (size_t)(l*Nn + qr0) * INNER + h*DHd;
    size_t b1i = (size_t)(l*Nn + qr0 + 8) * INNER + h*DHd;
    #pragma unroll
    for (int nt = 0; nt < 8; nt++) {
        int col = nt*8 + tig*2;
        float v0 = o[nt][0]*inv0, v1 = o[nt][1]*inv0;
        float v2 = o[nt][2]*inv1, v3 = o[nt][3]*inv1;
        __nv_bfloat16 h0 = __float2bfloat16_rn(v0), h1 = __float2bfloat16_rn(v1);
        __nv_bfloat16 h2 = __float2bfloat16_rn(v2), h3 = __float2bfloat16_rn(v3);
        *(__nv_bfloat162*)(gaoh + b0i + col) = __halves2bfloat162(h0, h1);
        *(__nv_bfloat162*)(gaol + b0i + col) = __halves2bfloat162(
            __float2bfloat16_rn(v0 - __bfloat162float(h0)),
            __float2bfloat16_rn(v1 - __bfloat162float(h1)));
        *(__nv_bfloat162*)(gaoh + b1i + col) = __halves2bfloat162(h2, h3);
        *(__nv_bfloat162*)(gaol + b1i + col) = __halves2bfloat162(
            __float2bfloat16_rn(v2 - __bfloat162float(h2)),
            __float2bfloat16_rn(v3 - __bfloat162float(h3)));
    }
}

// ---------------------------------------------------------------------------
extern "C" void kernel_launch(void* const* d_in, const int* in_sizes, int n_in,
                              void* d_out, int out_size) {
    const float* x  = (const float*)d_in[0];
    const float* Wq = (const float*)d_in[1];
    const float* Wk = (const float*)d_in[2];
    const float* Wv = (const float*)d_in[3];
    const float* Wo = (const float*)d_in[4];
    const float* bo = (const float*)d_in[5];
    const unsigned char* mask = (const unsigned char*)d_in[6];
    float* out = (float*)d_out;

    mask_convert_kernel<<<1, 256>>>(mask);

    // One-time hi/lo splits
    __nv_bfloat16 *p_gxh, *p_gxl, *p_wqh, *p_wql, *p_wkh, *p_wkl;
    __nv_bfloat16 *p_wvh, *p_wvl, *p_woh, *p_wol;
    cudaGetSymbolAddress((void**)&p_gxh, gxh);
    cudaGetSymbolAddress((void**)&p_gxl, gxl);
    cudaGetSymbolAddress((void**)&p_wqh, gwqh);
    cudaGetSymbolAddress((void**)&p_wql, gwql);
    cudaGetSymbolAddress((void**)&p_wkh, gwkh);
    cudaGetSymbolAddress((void**)&p_wkl, gwkl);
    cudaGetSymbolAddress((void**)&p_wvh, gwvh);
    cudaGetSymbolAddress((void**)&p_wvl, gwvl);
    cudaGetSymbolAddress((void**)&p_woh, gwoh);
    cudaGetSymbolAddress((void**)&p_wol, gwol);

    split_kernel<<<(Ld*Nn*DIN/4 + 255)/256, 256>>>(x, p_gxh, p_gxl, Ld*Nn*DIN/4);
    split_kernel<<<(INNER*DIN/4 + 255)/256, 256>>>(Wq, p_wqh, p_wql, INNER*DIN/4);
    split_kernel<<<(INNER*DIN/4 + 255)/256, 256>>>(Wk, p_wkh, p_wkl, INNER*DIN/4);
    split_kernel<<<(INNER*DIN/4 + 255)/256, 256>>>(Wv, p_wvh, p_wvl, INNER*DIN/4);
    split_kernel<<<(DOUT*INNER/4 + 255)/256, 256>>>(Wo, p_woh, p_wol, DOUT*INNER/4);

    cudaFuncSetAttribute(qkv_tc_kernel, cudaFuncAttributeMaxDynamicSharedMemorySize,
                         GS_BYTES);
    cudaFuncSetAttribute(oproj_tc_kernel, cudaFuncAttributeMaxDynamicSharedMemorySize,
                         GS_BYTES);
    cudaFuncSetAttribute(attn_mma_kernel, cudaFuncAttributeMaxDynamicSharedMemorySize,
                         A_SMEM_BYTES);

    qkv_tc_kernel<<<dim3(INNER/128, (Ld*Nn)/128, 3), 256, GS_BYTES>>>();

    attn_mma_kernel<<<dim3(Nn/64, Hh, Ld), 128, A_SMEM_BYTES>>>();

    oproj_tc_kernel<<<dim3(DOUT/128, (Ld*Nn)/128), 256, GS_BYTES>>>(bo, out);
}

// round 7
// speedup vs baseline: 1.0902x; 1.0902x over previous
#include <cuda_runtime.h>
#include <cuda_bf16.h>
#include <math.h>
#include <cstdint>

// Problem constants
#define Ld 4
#define Nn 2048
#define DIN 1024
#define Hh 8
#define DHd 64
#define INNER 512
#define DOUT 1024
#define SCALEF 0.125f   // 64^-0.5

// ---------------------------------------------------------------------------
// Scratch (device globals) — all intermediates live as bf16 hi/lo pairs
// ---------------------------------------------------------------------------
__device__ __nv_bfloat16 gxh[(size_t)Ld*Nn*DIN], gxl[(size_t)Ld*Nn*DIN];
__device__ __nv_bfloat16 gwqh[INNER*DIN], gwql[INNER*DIN];
__device__ __nv_bfloat16 gwkh[INNER*DIN], gwkl[INNER*DIN];
__device__ __nv_bfloat16 gwvh[INNER*DIN], gwvl[INNER*DIN];
__device__ __nv_bfloat16 gwoh[DOUT*INNER], gwol[DOUT*INNER];
__device__ __nv_bfloat16 gqh[(size_t)Ld*Hh*Nn*DHd], gql[(size_t)Ld*Hh*Nn*DHd];
__device__ __nv_bfloat16 gkh[(size_t)Ld*Hh*Nn*DHd], gkl[(size_t)Ld*Hh*Nn*DHd];
__device__ __nv_bfloat16 gvh[(size_t)Ld*Hh*Nn*DHd], gvl[(size_t)Ld*Hh*Nn*DHd];
__device__ __nv_bfloat16 gaoh[(size_t)Ld*Nn*INNER], gaol[(size_t)Ld*Nn*INNER];
__device__ float g_mask[Ld*Nn];

// ===========================================================================
// Helpers
// ===========================================================================
__device__ __forceinline__ void mma_bf16(float* c, const uint32_t* a, const uint32_t* b) {
    asm volatile(
        "mma.sync.aligned.m16n8k16.row.col.f32.bf16.bf16.f32 "
        "{%0,%1,%2,%3}, {%4,%5,%6,%7}, {%8,%9}, {%0,%1,%2,%3};"
        : "+f"(c[0]), "+f"(c[1]), "+f"(c[2]), "+f"(c[3])
        : "r"(a[0]), "r"(a[1]), "r"(a[2]), "r"(a[3]), "r"(b[0]), "r"(b[1]));
}

#define LDMX4(r, a) \
    asm volatile("ldmatrix.sync.aligned.m8n8.x4.shared.b16 {%0,%1,%2,%3}, [%4];" \
        : "=r"((r)[0]), "=r"((r)[1]), "=r"((r)[2]), "=r"((r)[3]) : "r"(a))

#define LDMX4T(r, a) \
    asm volatile("ldmatrix.sync.aligned.m8n8.x4.trans.shared.b16 {%0,%1,%2,%3}, [%4];" \
        : "=r"((r)[0]), "=r"((r)[1]), "=r"((r)[2]), "=r"((r)[3]) : "r"(a))

__device__ __forceinline__ uint32_t smem_to_u32(const void* p) {
    uint32_t a;
    asm("{ .reg .u64 t; cvta.to.shared.u64 t, %1; cvt.u32.u64 %0, t; }" : "=r"(a) : "l"(p));
    return a;
}

__device__ __forceinline__ uint32_t packbf2(float x, float y) {
    __nv_bfloat162 h = __floats2bfloat162_rn(x, y);
    return *reinterpret_cast<uint32_t*>(&h);
}

// Fast exp on the FMA pipe (no MUFU); handles big-negative mask bias via clamp.
__device__ __forceinline__ float fast_exp(float x) {
    float t = fmaxf(x * 1.4426950408889634f, -126.0f);
    int ni = __float2int_rn(t);
    float r = t - (float)ni;
    float p = 1.5403530e-4f;
    p = fmaf(p, r, 1.3333558e-3f);
    p = fmaf(p, r, 9.6181291e-3f);
    p = fmaf(p, r, 5.5504109e-2f);
    p = fmaf(p, r, 2.4022651e-1f);
    p = fmaf(p, r, 6.9314718e-1f);
    p = fmaf(p, r, 1.0f);
    return __int_as_float(__float_as_int(p) + (ni << 23));
}

// ===========================================================================
// Mask dtype detection + normalization
// ===========================================================================
__global__ void mask_convert_kernel(const unsigned char* __restrict__ raw) {
    __shared__ int flag_float, flag_big;
    int tid = threadIdx.x;
    if (tid == 0) { flag_float = 0; flag_big = 0; }
    __syncthreads();
    const unsigned int* w = (const unsigned int*)raw;
    for (int i = tid; i < 2048; i += blockDim.x) {
        unsigned int v = w[i];
        if (v == 0x3F800000u) atomicOr(&flag_float, 1);
        else if (v > 1u)      atomicOr(&flag_big, 1);
    }
    __syncthreads();
    bool isfloat = (flag_float != 0);
    bool isbyte  = (!isfloat) && (flag_big != 0);
    for (int i = tid; i < Ld*Nn; i += blockDim.x) {
        unsigned int v;
        if (isbyte) v = raw[i];
        else        v = ((const unsigned int*)raw)[i];
        g_mask[i] = (v != 0u) ? 1.0f : 0.0f;
    }
}

// ===========================================================================
// One-time fp32 -> bf16 hi/lo split (elementwise, float4-vectorized)
// ===========================================================================
__global__ void split_kernel(const float* __restrict__ in,
                             __nv_bfloat16* __restrict__ hi,
                             __nv_bfloat16* __restrict__ lo, int n4) {
    int i = blockIdx.x * 256 + threadIdx.x;
    if (i >= n4) return;
    float4 v = ((const float4*)in)[i];
    __nv_bfloat16 h0 = __float2bfloat16_rn(v.x);
    __nv_bfloat16 h1 = __float2bfloat16_rn(v.y);
    __nv_bfloat16 h2 = __float2bfloat16_rn(v.z);
    __nv_bfloat16 h3 = __float2bfloat16_rn(v.w);
    ((__nv_bfloat162*)hi)[i*2]   = __halves2bfloat162(h0, h1);
    ((__nv_bfloat162*)hi)[i*2+1] = __halves2bfloat162(h2, h3);
    ((__nv_bfloat162*)lo)[i*2]   = __halves2bfloat162(
        __float2bfloat16_rn(v.x - __bfloat162float(h0)),
        __float2bfloat16_rn(v.y - __bfloat162float(h1)));
    ((__nv_bfloat162*)lo)[i*2+1] = __halves2bfloat162(
        __float2bfloat16_rn(v.z - __bfloat162float(h2)),
        __float2bfloat16_rn(v.w - __bfloat162float(h3)));
}

// ===========================================================================
// bf16 GEMM core: C[128 x 64] = A[128 x K] * B[64 x K]^T
// Pre-split hi/lo bf16 inputs. 256 threads, 8 warps (4m x 2n), warp 32x32.
// R5 occupancy profile (32 accum regs) + R6 instruction profile (ldmatrix,
// no in-loop conversion).
// ===========================================================================
#define GS_ATS 72
#define GS_ABYTES (128 * GS_ATS)         // elems per A tile
#define GS_BBYTES (64 * GS_ATS)          // elems per B tile
#define GS_BYTES ((2 * GS_ABYTES + 2 * GS_BBYTES) * 2)

struct CFrag { float c[2][4][4]; };

__device__ __forceinline__ void gemm_tc(
    const __nv_bfloat16* __restrict__ Ah_g, const __nv_bfloat16* __restrict__ Al_g, int lda,
    const __nv_bfloat16* __restrict__ Bh_g, const __nv_bfloat16* __restrict__ Bl_g, int ldb,
    int Kdim, __nv_bfloat16* sm, CFrag& f)
{
    const int tid = threadIdx.x, lane = tid & 31, wid = tid >> 5;
    const int warp_m = wid >> 1, warp_n = wid & 1;
    const int lrow = lane & 15, lcol = (lane >> 4) << 3;
    const int brow = (lane & 7) + ((lane >> 3) & 1) * 8;

    __nv_bfloat16* Ah = sm;
    __nv_bfloat16* Al = sm + GS_ABYTES;
    __nv_bfloat16* Bh = sm + 2 * GS_ABYTES;
    __nv_bfloat16* Bl = sm + 2 * GS_ABYTES + GS_BBYTES;
    const uint32_t ah_u = smem_to_u32(Ah), al_u = smem_to_u32(Al);
    const uint32_t bh_u = smem_to_u32(Bh), bl_u = smem_to_u32(Bl);

    #pragma unroll
    for (int mt = 0; mt < 2; mt++)
        #pragma unroll
        for (int nt = 0; nt < 4; nt++)
            #pragma unroll
            for (int i = 0; i < 4; i++) f.c[mt][nt][i] = 0.0f;

    for (int k0 = 0; k0 < Kdim; k0 += 64) {
        // A tile 128x64 (hi+lo): 1024 segments of 8 bf16
        #pragma unroll
        for (int it = 0; it < 4; it++) {
            int t = tid + it * 256;
            int r = t >> 3, c8 = (t & 7) << 3;
            *(uint4*)(Ah + r * GS_ATS + c8) = *(const uint4*)(Ah_g + (size_t)r * lda + k0 + c8);
            *(uint4*)(Al + r * GS_ATS + c8) = *(const uint4*)(Al_g + (size_t)r * lda + k0 + c8);
        }
        // B tile 64x64 (hi+lo): 512 segments
        #pragma unroll
        for (int it = 0; it < 2; it++) {
            int t = tid + it * 256;
            int r = t >> 3, c8 = (t & 7) << 3;
            *(uint4*)(Bh + r * GS_ATS + c8) = *(const uint4*)(Bh_g + (size_t)r * ldb + k0 + c8);
            *(uint4*)(Bl + r * GS_ATS + c8) = *(const uint4*)(Bl_g + (size_t)r * ldb + k0 + c8);
        }
        __syncthreads();

        #pragma unroll
        for (int ks = 0; ks < 4; ks++) {
            const int kk = ks * 16;
            uint32_t ahf[2][4], alf[2][4];
            #pragma unroll
            for (int mt = 0; mt < 2; mt++) {
                uint32_t off = (uint32_t)((warp_m*32 + mt*16 + lrow) * GS_ATS + kk + lcol) * 2;
                LDMX4(ahf[mt], ah_u + off);
                LDMX4(alf[mt], al_u + off);
            }
            #pragma unroll
            for (int ng = 0; ng < 2; ng++) {
                uint32_t off = (uint32_t)((warp_n*32 + ng*16 + brow) * GS_ATS + kk + lcol) * 2;
                uint32_t kh4[4], kl4[4];
                LDMX4(kh4, bh_u + off);
                LDMX4(kl4, bl_u + off);
                uint32_t b0h[2] = {kh4[0], kh4[2]}, b1h[2] = {kh4[1], kh4[3]};
                uint32_t b0l[2] = {kl4[0], kl4[2]}, b1l[2] = {kl4[1], kl4[3]};
                #pragma unroll
                for (int mt = 0; mt < 2; mt++) {
                    mma_bf16(f.c[mt][ng*2],   ahf[mt], b0h);
                    mma_bf16(f.c[mt][ng*2],   ahf[mt], b0l);
                    mma_bf16(f.c[mt][ng*2],   alf[mt], b0h);
                    mma_bf16(f.c[mt][ng*2+1], ahf[mt], b1h);
                    mma_bf16(f.c[mt][ng*2+1], ahf[mt], b1l);
                    mma_bf16(f.c[mt][ng*2+1], alf[mt], b1h);
                }
            }
        }
        __syncthreads();
    }
}

// ---------------------------------------------------------------------------
// QKV projection: grid (8 e-tiles==heads, 64 m-tiles, 3 matrices).
// Output written head-split as bf16 hi/lo; q pre-scaled by SCALEF.
// ---------------------------------------------------------------------------
__global__ __launch_bounds__(256)
void qkv_tc_kernel() {
    extern __shared__ __nv_bfloat16 smg[];
    const int which = blockIdx.z;
    const __nv_bfloat16 *Wh, *Wl;
    __nv_bfloat16 *oh, *ol;
    float scale;
    if (which == 0)      { Wh = gwqh; Wl = gwql; oh = gqh; ol = gql; scale = SCALEF; }
    else if (which == 1) { Wh = gwkh; Wl = gwkl; oh = gkh; ol = gkl; scale = 1.0f; }
    else                 { Wh = gwvh; Wl = gwvl; oh = gvh; ol = gvl; scale = 1.0f; }

    const int m0 = blockIdx.y * 128, e0 = blockIdx.x * 64;
    const int head = blockIdx.x;
    CFrag f;
    gemm_tc(gxh + (size_t)m0 * DIN, gxl + (size_t)m0 * DIN, DIN,
            Wh + (size_t)e0 * DIN, Wl + (size_t)e0 * DIN, DIN, DIN, smg, f);

    const int tid = threadIdx.x, lane = tid & 31, wid = tid >> 5;
    const int gid = lane >> 2, tig = lane & 3;
    const int warp_m = wid >> 1, warp_n = wid & 1;

    #pragma unroll
    for (int mt = 0; mt < 2; mt++) {
        #pragma unroll
        for (int rr = 0; rr < 2; rr++) {
            int m = m0 + warp_m*32 + mt*16 + gid + rr*8;
            int l = m >> 11, n = m & 2047;
            size_t base = ((size_t)((l*Hh + head)*Nn + n)) * DHd;
            #pragma unroll
            for (int nt = 0; nt < 4; nt++) {
                int d = warp_n*32 + nt*8 + tig*2;
                float v0 = f.c[mt][nt][rr*2]   * scale;
                float v1 = f.c[mt][nt][rr*2+1] * scale;
                __nv_bfloat16 h0 = __float2bfloat16_rn(v0);
                __nv_bfloat16 h1 = __float2bfloat16_rn(v1);
                *(__nv_bfloat162*)(oh + base + d) = __halves2bfloat162(h0, h1);
                *(__nv_bfloat162*)(ol + base + d) = __halves2bfloat162(
                    __float2bfloat16_rn(v0 - __bfloat162float(h0)),
                    __float2bfloat16_rn(v1 - __bfloat162float(h1)));
            }
        }
    }
}

// ---------------------------------------------------------------------------
// Output projection: grid (16 o-tiles, 64 m-tiles), fp32 out + bias
// ---------------------------------------------------------------------------
__global__ __launch_bounds__(256)
void oproj_tc_kernel(const float* __restrict__ bo, float* __restrict__ out) {
    extern __shared__ __nv_bfloat16 smg[];
    const int m0 = blockIdx.y * 128, o0 = blockIdx.x * 64;
    CFrag f;
    gemm_tc(gaoh + (size_t)m0 * INNER, gaol + (size_t)m0 * INNER, INNER,
            gwoh + (size_t)o0 * INNER, gwol + (size_t)o0 * INNER, INNER, INNER, smg, f);

    const int tid = threadIdx.x, lane = tid & 31, wid = tid >> 5;
    const int gid = lane >> 2, tig = lane & 3;
    const int warp_m = wid >> 1, warp_n = wid & 1;

    #pragma unroll
    for (int mt = 0; mt < 2; mt++) {
        #pragma unroll
        for (int rr = 0; rr < 2; rr++) {
            int m = m0 + warp_m*32 + mt*16 + gid + rr*8;
            float* dst = out + (size_t)m * DOUT + o0;
            #pragma unroll
            for (int nt = 0; nt < 4; nt++) {
                int col = warp_n*32 + nt*8 + tig*2;
                float2 b = *(const float2*)(bo + o0 + col);
                *(float2*)(dst + col) = make_float2(f.c[mt][nt][rr*2]   + b.x,
                                                    f.c[mt][nt][rr*2+1] + b.y);
            }
        }
    }
}

// ===========================================================================
// Flash attention on HMMA, bf16 hi/lo inputs (validated R6, unchanged)
// ===========================================================================
#define ATS 72
#define A_QH 0
#define A_QL 4608
#define A_KH 9216
#define A_KL 13824
#define A_VH 18432
#define A_VL 23040
#define A_BIAS_BYTES 55296
#define A_SMEM_BYTES  55552

__global__ __launch_bounds__(128, 3)
void attn_mma_kernel() {
    extern __shared__ char sb[];
    __nv_bfloat16* Qh = (__nv_bfloat16*)sb;
    __nv_bfloat16* Ql = Qh + A_QL;
    __nv_bfloat16* Kh = Qh + A_KH;
    __nv_bfloat16* Kl = Qh + A_KL;
    __nv_bfloat16* Vh = Qh + A_VH;
    __nv_bfloat16* Vl = Qh + A_VL;
    float* bias = (float*)(sb + A_BIAS_BYTES);

    const int qb = blockIdx.x, h = blockIdx.y, l = blockIdx.z;
    const int tid = threadIdx.x;
    const int wid = tid >> 5, lane = tid & 31;
    const int gid = lane >> 2, tig = lane & 3;
    const int q0 = qb * 64;
    const size_t hb = (size_t)((l*Hh + h) * Nn) * DHd;

    #pragma unroll
    for (int it = 0; it < 4; it++) {
        int t = tid + it * 128;
        int r = t >> 3, c8 = (t & 7) << 3;
        *(uint4*)(Qh + r*ATS + c8) = *(const uint4*)(gqh + hb + (size_t)(q0 + r)*DHd + c8);
        *(uint4*)(Ql + r*ATS + c8) = *(const uint4*)(gql + hb + (size_t)(q0 + r)*DHd + c8);
    }

    const int lrow = lane & 15, lcol = (lane >> 4) << 3;
    const int brow = (lane & 7) + ((lane >> 3) & 1) * 8;
    const uint32_t qh_u = smem_to_u32(Qh), ql_u = smem_to_u32(Ql);
    const uint32_t kh_u = smem_to_u32(Kh), kl_u = smem_to_u32(Kl);
    const int l4 = lane & 7, grp = lane >> 3;
    const int vrow = l4 + ((grp & 1) << 3);
    const int vcol = (grp >> 1) << 3;
    const uint32_t vh_base = smem_to_u32(Vh) + (uint32_t)(vrow * ATS + vcol) * 2;
    const uint32_t vl_base = smem_to_u32(Vl) + (uint32_t)(vrow * ATS + vcol) * 2;

    float o[8][4];
    #pragma unroll
    for (int nt = 0; nt < 8; nt++)
        #pragma unroll
        for (int i = 0; i < 4; i++) o[nt][i] = 0.0f;
    float m0 = -1e30f, m1 = -1e30f, l0 = 0.0f, l1 = 0.0f;

    for (int kb = 0; kb < Nn / 64; kb++) {
        __syncthreads();
        #pragma unroll
        for (int it = 0; it < 4; it++) {
            int t = tid + it * 128;
            int r = t >> 3, c8 = (t & 7) << 3;
            size_t src = hb + (size_t)(kb*64 + r) * DHd + c8;
            *(uint4*)(Kh + r*ATS + c8) = *(const uint4*)(gkh + src);
            *(uint4*)(Kl + r*ATS + c8) = *(const uint4*)(gkl + src);
            *(uint4*)(Vh + r*ATS + c8) = *(const uint4*)(gvh + src);
            *(uint4*)(Vl + r*ATS + c8) = *(const uint4*)(gvl + src);
        }
        if (tid < 64) bias[tid] = (g_mask[l*Nn + kb*64 + tid] - 1.0f) * 1e9f;
        __syncthreads();

        float sfr[8][4];
        #pragma unroll
        for (int nt = 0; nt < 8; nt++)
            #pragma unroll
            for (int i = 0; i < 4; i++) sfr[nt][i] = 0.0f;

        #pragma unroll
        for (int ks = 0; ks < 4; ks++) {
            const int kk = ks * 16;
            uint32_t aqh[4], aql[4];
            uint32_t qoff = (uint32_t)((wid*16 + lrow) * ATS + kk + lcol) * 2;
            LDMX4(aqh, qh_u + qoff);
            LDMX4(aql, ql_u + qoff);
            #pragma unroll
            for (int ng = 0; ng < 4; ng++) {
                uint32_t koff = (uint32_t)((ng*16 + brow) * ATS + kk + lcol) * 2;
                uint32_t kh4[4], kl4[4];
                LDMX4(kh4, kh_u + koff);
                LDMX4(kl4, kl_u + koff);
                uint32_t b0h[2] = {kh4[0], kh4[2]}, b1h[2] = {kh4[1], kh4[3]};
                uint32_t b0l[2] = {kl4[0], kl4[2]}, b1l[2] = {kl4[1], kl4[3]};
                mma_bf16(sfr[ng*2],   aqh, b0h);
                mma_bf16(sfr[ng*2],   aqh, b0l);
                mma_bf16(sfr[ng*2],   aql, b0h);
                mma_bf16(sfr[ng*2+1], aqh, b1h);
                mma_bf16(sfr[ng*2+1], aqh, b1l);
                mma_bf16(sfr[ng*2+1], aql, b1h);
            }
        }

        float mx0 = -1e30f, mx1 = -1e30f;
        #pragma unroll
        for (int nt = 0; nt < 8; nt++) {
            float2 b2 = *(const float2*)(bias + nt*8 + tig*2);
            sfr[nt][0] += b2.x; sfr[nt][1] += b2.y;
            sfr[nt][2] += b2.x; sfr[nt][3] += b2.y;
            mx0 = fmaxf(mx0, fmaxf(sfr[nt][0], sfr[nt][1]));
            mx1 = fmaxf(mx1, fmaxf(sfr[nt][2], sfr[nt][3]));
        }
        mx0 = fmaxf(mx0, __shfl_xor_sync(0xFFFFFFFFu, mx0, 1));
        mx0 = fmaxf(mx0, __shfl_xor_sync(0xFFFFFFFFu, mx0, 2));
        mx1 = fmaxf(mx1, __shfl_xor_sync(0xFFFFFFFFu, mx1, 1));
        mx1 = fmaxf(mx1, __shfl_xor_sync(0xFFFFFFFFu, mx1, 2));

        float mn0 = fmaxf(m0, mx0), mn1 = fmaxf(m1, mx1);
        float sc0 = fast_exp(m0 - mn0), sc1 = fast_exp(m1 - mn1);
        m0 = mn0; m1 = mn1;

        float rs0 = 0.0f, rs1 = 0.0f;
        uint32_t ph[8][2], pl[8][2];
        #pragma unroll
        for (int nt = 0; nt < 8; nt++) {
            float p0 = fast_exp(sfr[nt][0] - m0);
            float p1 = fast_exp(sfr[nt][1] - m0);
            float p2 = fast_exp(sfr[nt][2] - m1);
            float p3 = fast_exp(sfr[nt][3] - m1);
            rs0 += p0 + p1; rs1 += p2 + p3;
            __nv_bfloat16 h0 = __float2bfloat16_rn(p0);
            __nv_bfloat16 h1 = __float2bfloat16_rn(p1);
            __nv_bfloat16 h2 = __float2bfloat16_rn(p2);
            __nv_bfloat16 h3 = __float2bfloat16_rn(p3);
            ph[nt][0] = packbf2(__bfloat162float(h0), __bfloat162float(h1));
            ph[nt][1] = packbf2(__bfloat162float(h2), __bfloat162float(h3));
            pl[nt][0] = packbf2(p0 - __bfloat162float(h0), p1 - __bfloat162float(h1));
            pl[nt][1] = packbf2(p2 - __bfloat162float(h2), p3 - __bfloat162float(h3));
        }
        rs0 += __shfl_xor_sync(0xFFFFFFFFu, rs0, 1);
        rs0 += __shfl_xor_sync(0xFFFFFFFFu, rs0, 2);
        rs1 += __shfl_xor_sync(0xFFFFFFFFu, rs1, 1);
        rs1 += __shfl_xor_sync(0xFFFFFFFFu, rs1, 2);
        l0 = l0 * sc0 + rs0;
        l1 = l1 * sc1 + rs1;

        #pragma unroll
        for (int nt = 0; nt < 8; nt++) {
            o[nt][0] *= sc0; o[nt][1] *= sc0;
            o[nt][2] *= sc1; o[nt][3] *= sc1;
        }

        #pragma unroll
        for (int ks = 0; ks < 4; ks++) {
            uint32_t aph[4] = { ph[2*ks][0], ph[2*ks][1], ph[2*ks+1][0], ph[2*ks+1][1] };
            uint32_t apl[4] = { pl[2*ks][0], pl[2*ks][1], pl[2*ks+1][0], pl[2*ks+1][1] };
            #pragma unroll
            for (int dhc = 0; dhc < 4; dhc++) {
                uint32_t off = (uint32_t)(ks * 16 * ATS + dhc * 16) * 2;
                uint32_t bvh[4], bvl[4];
                LDMX4T(bvh, vh_base + off);
                LDMX4T(bvl, vl_base + off);
                int nt = dhc * 2;
                mma_bf16(o[nt],   aph, bvh);
                mma_bf16(o[nt],   aph, bvl);
                mma_bf16(o[nt],   apl, bvh);
                mma_bf16(o[nt+1], aph, bvh + 2);
                mma_bf16(o[nt+1], aph, bvl + 2);
                mma_bf16(o[nt+1], apl, bvh + 2);
            }
        }
    }

    float inv0 = 1.0f / l0, inv1 = 1.0f / l1;
    int qr0 = q0 + wid*16 + gid;
    size_t b0i = (size_t)(l*Nn + qr0) * INNER + h*DHd;
    size_t b1i = (size_t)(l*Nn + qr0 + 8) * INNER + h*DHd;
    #pragma unroll
    for (int nt = 0; nt < 8; nt++) {
        int col = nt*8 + tig*2;
        float v0 = o[nt][0]*inv0, v1 = o[nt][1]*inv0;
        float v2 = o[nt][2]*inv1, v3 = o[nt][3]*inv1;
        __nv_bfloat16 h0 = __float2bfloat16_rn(v0), h1 = __float2bfloat16_rn(v1);
        __nv_bfloat16 h2 = __float2bfloat16_rn(v2), h3 = __float2bfloat16_rn(v3);
        *(__nv_bfloat162*)(gaoh + b0i + col) = __halves2bfloat162(h0, h1);
        *(__nv_bfloat162*)(gaol + b0i + col) = __halves2bfloat162(
            __float2bfloat16_rn(v0 - __bfloat162float(h0)),
            __float2bfloat16_rn(v1 - __bfloat162float(h1)));
        *(__nv_bfloat162*)(gaoh + b1i + col) = __halves2bfloat162(h2, h3);
        *(__nv_bfloat162*)(gaol + b1i + col) = __halves2bfloat162(
            __float2bfloat16_rn(v2 - __bfloat162float(h2)),
            __float2bfloat16_rn(v3 - __bfloat162float(h3)));
    }
}

// ---------------------------------------------------------------------------
extern "C" void kernel_launch(void* const* d_in, const int* in_sizes, int n_in,
                              void* d_out, int out_size) {
    const float* x  = (const float*)d_in[0];
    const float* Wq = (const float*)d_in[1];
    const float* Wk = (const float*)d_in[2];
    const float* Wv = (const float*)d_in[3];
    const float* Wo = (const float*)d_in[4];
    const float* bo = (const float*)d_in[5];
    const unsigned char* mask = (const unsigned char*)d_in[6];
    float* out = (float*)d_out;

    mask_convert_kernel<<<1, 256>>>(mask);

    __nv_bfloat16 *p_gxh, *p_gxl, *p_wqh, *p_wql, *p_wkh, *p_wkl;
    __nv_bfloat16 *p_wvh, *p_wvl, *p_woh, *p_wol;
    cudaGetSymbolAddress((void**)&p_gxh, gxh);
    cudaGetSymbolAddress((void**)&p_gxl, gxl);
    cudaGetSymbolAddress((void**)&p_wqh, gwqh);
    cudaGetSymbolAddress((void**)&p_wql, gwql);
    cudaGetSymbolAddress((void**)&p_wkh, gwkh);
    cudaGetSymbolAddress((void**)&p_wkl, gwkl);
    cudaGetSymbolAddress((void**)&p_wvh, gwvh);
    cudaGetSymbolAddress((void**)&p_wvl, gwvl);
    cudaGetSymbolAddress((void**)&p_woh, gwoh);
    cudaGetSymbolAddress((void**)&p_wol, gwol);

    split_kernel<<<(Ld*Nn*DIN/4 + 255)/256, 256>>>(x, p_gxh, p_gxl, Ld*Nn*DIN/4);
    split_kernel<<<(INNER*DIN/4 + 255)/256, 256>>>(Wq, p_wqh, p_wql, INNER*DIN/4);
    split_kernel<<<(INNER*DIN/4 + 255)/256, 256>>>(Wk, p_wkh, p_wkl, INNER*DIN/4);
    split_kernel<<<(INNER*DIN/4 + 255)/256, 256>>>(Wv, p_wvh, p_wvl, INNER*DIN/4);
    split_kernel<<<(DOUT*INNER/4 + 255)/256, 256>>>(Wo, p_woh, p_wol, DOUT*INNER/4);

    cudaFuncSetAttribute(qkv_tc_kernel, cudaFuncAttributeMaxDynamicSharedMemorySize,
                         GS_BYTES);
    cudaFuncSetAttribute(oproj_tc_kernel, cudaFuncAttributeMaxDynamicSharedMemorySize,
                         GS_BYTES);
    cudaFuncSetAttribute(attn_mma_kernel, cudaFuncAttributeMaxDynamicSharedMemorySize,
                         A_SMEM_BYTES);

    qkv_tc_kernel<<<dim3(INNER/64, (Ld*Nn)/128, 3), 256, GS_BYTES>>>();

    attn_mma_kernel<<<dim3(Nn/64, Hh, Ld), 128, A_SMEM_BYTES>>>();

    oproj_tc_kernel<<<dim3(DOUT/64, (Ld*Nn)/128), 256, GS_BYTES>>>(bo, out);
}